// round 4
// baseline (speedup 1.0000x reference)
#include <cuda_runtime.h>
#include <cuda_fp16.h>

#define NN 50000
#define NE 600000
#define FI 128
#define HD 64
#define NC 40
#define SCB 512
#define NBLK ((NN + SCB - 1) / SCB)   // 98
#define KH 10

// ---------------- device scratch (static, allocation-free) ----------------
__device__ float   g_x1[NN * HD];          // x @ W1 (fp32, for final)
__device__ __half2 g_h16[KH + 1][NN * 32]; // h buffers: [0]=x1 fp16, [l]=T^l x1
__device__ float   g_deg[NN];
__device__ float   g_dinv[NN];
__device__ int     g_cnt[NN];
__device__ int     g_fill[NN];
__device__ int     g_rowptr[NN + 1];
__device__ int     g_bsum[NBLK];
__device__ int     g_boff[NBLK];
__device__ float2  g_edge[NE];             // (col as int bits, normalized weight)

// ---------------- preprocessing ----------------
__global__ void k_init() {
    int i = blockIdx.x * blockDim.x + threadIdx.x;
    if (i < NN) { g_deg[i] = 1.0f; g_cnt[i] = 0; g_fill[i] = 0; }
}

__global__ void k_degree(const int* __restrict__ ei, const float* __restrict__ ew) {
    int e = blockIdx.x * blockDim.x + threadIdx.x;
    if (e < NE) {
        int r = ei[e];
        atomicAdd(&g_deg[r], ew[e]);
        atomicAdd(&g_cnt[r], 1);
    }
}

// Stage A: per-block exclusive scan of g_cnt -> g_rowptr (pre-offset) + dinv fused.
__global__ void __launch_bounds__(SCB) k_scanA() {
    __shared__ int wsum[16];
    int t = threadIdx.x;
    int i = blockIdx.x * SCB + t;
    int v = (i < NN) ? g_cnt[i] : 0;
    if (i < NN) {
        float d = g_deg[i];
        g_dinv[i] = (d > 0.0f) ? rsqrtf(fmaxf(d, 1e-12f)) : 0.0f;
    }
    int lane = t & 31, w = t >> 5;
    int inc = v;
#pragma unroll
    for (int o = 1; o < 32; o <<= 1) {
        int u = __shfl_up_sync(0xFFFFFFFFu, inc, o);
        if (lane >= o) inc += u;
    }
    if (lane == 31) wsum[w] = inc;
    __syncthreads();
    if (w == 0) {
        int s = (lane < 16) ? wsum[lane] : 0;
#pragma unroll
        for (int o = 1; o < 16; o <<= 1) {
            int u = __shfl_up_sync(0xFFFFFFFFu, s, o);
            if (lane >= o) s += u;
        }
        if (lane < 16) wsum[lane] = s;
    }
    __syncthreads();
    int wbase = (w > 0) ? wsum[w - 1] : 0;
    if (i < NN) g_rowptr[i] = wbase + inc - v;
    if (t == 0) g_bsum[blockIdx.x] = wsum[15];
}

// Stage B: exclusive scan of 98 block sums.
__global__ void k_scanB() {
    __shared__ int ws[4];
    int t = threadIdx.x, lane = t & 31, w = t >> 5;
    int v = (t < NBLK) ? g_bsum[t] : 0;
    int inc = v;
#pragma unroll
    for (int o = 1; o < 32; o <<= 1) {
        int u = __shfl_up_sync(0xFFFFFFFFu, inc, o);
        if (lane >= o) inc += u;
    }
    if (lane == 31) ws[w] = inc;
    __syncthreads();
    if (t == 0) {
        int s = 0;
#pragma unroll
        for (int k = 0; k < 4; k++) { int x = ws[k]; ws[k] = s; s += x; }
    }
    __syncthreads();
    if (t < NBLK) g_boff[t] = ws[w] + inc - v;
    if (t == 0) g_rowptr[NN] = NE;
}

// Stage C: add block offsets.
__global__ void k_scanC() {
    int i = blockIdx.x * blockDim.x + threadIdx.x;
    if (i < NN) g_rowptr[i] += g_boff[i / SCB];
}

__global__ void k_fill(const int* __restrict__ ei, const float* __restrict__ ew) {
    int e = blockIdx.x * blockDim.x + threadIdx.x;
    if (e < NE) {
        int r = ei[e];
        int c = ei[NE + e];
        float w = ew[e] * g_dinv[r] * g_dinv[c];
        int p = g_rowptr[r] + atomicAdd(&g_fill[r], 1);
        g_edge[p] = make_float2(__int_as_float(c), w);
    }
}

// ---------------- GEMM1: x1 = x @ W1   [NN,128]x[128,64] -> [NN,64] ----------------
// Writes fp32 (g_x1) and fp16 (g_h16[0], propagation source).
__global__ void __launch_bounds__(256) k_gemm1(const float* __restrict__ x,
                                               const float* __restrict__ W1) {
    __shared__ float W1s[64 * 64];
    __shared__ float xs[64 * 68];
    int t  = threadIdx.x;
    int tx = t & 15;
    int ty = t >> 4;
    int nb = blockIdx.x * 64;

    float acc[4][4];
#pragma unroll
    for (int i = 0; i < 4; i++)
#pragma unroll
        for (int j = 0; j < 4; j++) acc[i][j] = 0.0f;

    for (int kh = 0; kh < 2; kh++) {
        __syncthreads();
        for (int i = t; i < 1024; i += 256)
            ((float4*)W1s)[i] = ((const float4*)(W1 + kh * 64 * 64))[i];
        for (int i = t; i < 1024; i += 256) {
            int r  = i >> 4;
            int kk = (i & 15) << 2;
            int n  = nb + r;
            float4 v = make_float4(0.f, 0.f, 0.f, 0.f);
            if (n < NN) v = *(const float4*)(x + n * FI + kh * 64 + kk);
            *(float4*)(xs + r * 68 + kk) = v;
        }
        __syncthreads();
#pragma unroll 8
        for (int k = 0; k < 64; k++) {
            float4 b4 = *(const float4*)(W1s + k * 64 + tx * 4);
#pragma unroll
            for (int i = 0; i < 4; i++) {
                float a = xs[(ty * 4 + i) * 68 + k];
                acc[i][0] += a * b4.x;
                acc[i][1] += a * b4.y;
                acc[i][2] += a * b4.z;
                acc[i][3] += a * b4.w;
            }
        }
    }
#pragma unroll
    for (int i = 0; i < 4; i++) {
        int n = nb + ty * 4 + i;
        if (n < NN) {
            *(float4*)(g_x1 + n * HD + tx * 4) =
                make_float4(acc[i][0], acc[i][1], acc[i][2], acc[i][3]);
            g_h16[0][n * 32 + tx * 2]     = __floats2half2_rn(acc[i][0], acc[i][1]);
            g_h16[0][n * 32 + tx * 2 + 1] = __floats2half2_rn(acc[i][2], acc[i][3]);
        }
    }
}

// ---------------- SpMM hop: warp per row, lane = one half2 (2 features) ----------------
// reads g_h16[l], writes g_h16[l+1]; fp32 accumulation, fp16 storage.
__global__ void __launch_bounds__(256) k_hop(int l) {
    int gw   = (blockIdx.x * blockDim.x + threadIdx.x) >> 5;
    int lane = threadIdx.x & 31;
    if (gw >= NN) return;

    const __half2* __restrict__ s = g_h16[l];
    __half2* __restrict__ d = g_h16[l + 1];

    int beg = g_rowptr[gw];
    int end = g_rowptr[gw + 1];

    float di = g_dinv[gw];
    float sw = di * di;                   // self-loop weight
    float2 self = __half22float2(s[gw * 32 + lane]);
    float ax = sw * self.x;
    float ay = sw * self.y;

    int e = beg;
    for (; e + 3 < end; e += 4) {
        float2 cw0 = g_edge[e];
        float2 cw1 = g_edge[e + 1];
        float2 cw2 = g_edge[e + 2];
        float2 cw3 = g_edge[e + 3];
        float2 h0 = __half22float2(s[__float_as_int(cw0.x) * 32 + lane]);
        float2 h1 = __half22float2(s[__float_as_int(cw1.x) * 32 + lane]);
        float2 h2 = __half22float2(s[__float_as_int(cw2.x) * 32 + lane]);
        float2 h3 = __half22float2(s[__float_as_int(cw3.x) * 32 + lane]);
        ax += cw0.y * h0.x + cw1.y * h1.x;
        ay += cw0.y * h0.y + cw1.y * h1.y;
        ax += cw2.y * h2.x + cw3.y * h3.x;
        ay += cw2.y * h2.y + cw3.y * h3.y;
    }
    for (; e < end; e++) {
        float2 cw = g_edge[e];
        float2 h0 = __half22float2(s[__float_as_int(cw.x) * 32 + lane]);
        ax += cw.y * h0.x;
        ay += cw.y * h0.y;
    }

    d[gw * 32 + lane] = __floats2half2_rn(ax, ay);
}

// ---------------- final: z = relu(C1*sum_l h_l + C2*x1 + b1); out = z @ W2 + b2 ----------
__global__ void __launch_bounds__(320) k_final(const float* __restrict__ b1,
                                               const float* __restrict__ W2,
                                               const float* __restrict__ b2,
                                               float* __restrict__ out) {
    __shared__ float W2t[NC * 68];
    __shared__ float zs[8 * 64];
    __shared__ float b1s[HD];

    int t = threadIdx.x;
    for (int i = t; i < HD * NC; i += 320) {
        int k = i / NC, c = i % NC;
        W2t[c * 68 + k] = W2[i];
    }
    if (t < HD) b1s[t] = b1[t];

    int node = t / NC;
    int cls  = t % NC;
    float b2v = b2[cls];
    __syncthreads();

    const float C1 = (1.0f - 0.1f) / 10.0f;  // 0.09
    const float C2 = 0.1f;
    int nb0 = blockIdx.x * 400;

    for (int it = 0; it < 50; it++) {
        int nb = nb0 + it * 8;
        // phase 1: 8 nodes x 32 half2 = 256 work items
        if (t < 256) {
            int n  = nb + (t >> 5);
            int fp = t & 31;
            float sx = 0.0f, sy = 0.0f;
#pragma unroll
            for (int l = 1; l <= KH; l++) {
                float2 v = __half22float2(g_h16[l][n * 32 + fp]);
                sx += v.x; sy += v.y;
            }
            float2 x1v = ((const float2*)g_x1)[n * 32 + fp];
            int r = (t >> 5) * 64 + fp * 2;
            zs[r]     = fmaxf(C1 * sx + C2 * x1v.x + b1s[fp * 2],     0.0f);
            zs[r + 1] = fmaxf(C1 * sy + C2 * x1v.y + b1s[fp * 2 + 1], 0.0f);
        }
        __syncthreads();
        // phase 2: one thread per (node, class)
        float s = b2v;
        const float* zr = zs + node * 64;
        const float* wr = W2t + cls * 68;
#pragma unroll
        for (int k = 0; k < 64; k += 4) {
            float4 zv = *(const float4*)(zr + k);
            float4 wv = *(const float4*)(wr + k);
            s += zv.x * wv.x + zv.y * wv.y + zv.z * wv.z + zv.w * wv.w;
        }
        out[(nb + node) * NC + cls] = s;
        __syncthreads();
    }
}

// ---------------- launch ----------------
extern "C" void kernel_launch(void* const* d_in, const int* in_sizes, int n_in,
                              void* d_out, int out_size) {
    const float* x  = (const float*)d_in[0];
    const int*   ei = (const int*)d_in[1];    // [2, NE]
    const float* ew = (const float*)d_in[2];
    const float* W1 = (const float*)d_in[3];  // [128, 64]
    const float* b1 = (const float*)d_in[4];
    const float* W2 = (const float*)d_in[5];  // [64, 40]
    const float* b2 = (const float*)d_in[6];
    float* out = (float*)d_out;

    k_init  <<<(NN + 255) / 256, 256>>>();
    k_degree<<<(NE + 255) / 256, 256>>>(ei, ew);
    k_scanA <<<NBLK, SCB>>>();
    k_scanB <<<1, 128>>>();
    k_scanC <<<(NN + 255) / 256, 256>>>();
    k_fill  <<<(NE + 255) / 256, 256>>>(ei, ew);
    k_gemm1 <<<(NN + 63) / 64, 256>>>(x, W1);

    int hop_blocks = (NN * 32 + 255) / 256;  // 6250
    for (int i = 0; i < KH; i++)
        k_hop<<<hop_blocks, 256>>>(i);

    k_final<<<125, 320>>>(b1, W2, b2, out);
}

// round 5
// speedup vs baseline: 1.2784x; 1.2784x over previous
#include <cuda_runtime.h>
#include <cuda_fp16.h>

#define NN 50000
#define NE 600000
#define FI 128
#define HD 64
#define NC 40
#define SCB 512
#define NBLK ((NN + SCB - 1) / SCB)   // 98
#define KH 10

// ---------------- device scratch (static, allocation-free) ----------------
__device__ float   g_x1[NN * HD];     // x @ W1 (fp32, for final)
__device__ __half2 g_sA[NN * 32];     // fp16 ping
__device__ __half2 g_sB[NN * 32];     // fp16 pong
__device__ float   g_acc[NN * HD];    // fp32 running sum of T^l x1
__device__ float   g_deg[NN];
__device__ float   g_dinv[NN];
__device__ int     g_cnt[NN];
__device__ int     g_fill[NN];
__device__ int     g_rowptr[NN + 1];
__device__ int     g_bsum[NBLK];
__device__ int     g_boff[NBLK];
__device__ float2  g_edge[NE];        // (col as int bits, normalized weight)

// ---------------- preprocessing ----------------
__global__ void k_init() {
    int i = blockIdx.x * blockDim.x + threadIdx.x;
    if (i < NN) { g_deg[i] = 1.0f; g_cnt[i] = 0; g_fill[i] = 0; }
}

__global__ void k_degree(const int* __restrict__ ei, const float* __restrict__ ew) {
    int e = blockIdx.x * blockDim.x + threadIdx.x;
    if (e < NE) {
        int r = ei[e];
        atomicAdd(&g_deg[r], ew[e]);
        atomicAdd(&g_cnt[r], 1);
    }
}

// Stage A: per-block exclusive scan of g_cnt -> g_rowptr (pre-offset) + dinv fused.
__global__ void __launch_bounds__(SCB) k_scanA() {
    __shared__ int wsum[16];
    int t = threadIdx.x;
    int i = blockIdx.x * SCB + t;
    int v = (i < NN) ? g_cnt[i] : 0;
    if (i < NN) {
        float d = g_deg[i];
        g_dinv[i] = (d > 0.0f) ? rsqrtf(fmaxf(d, 1e-12f)) : 0.0f;
    }
    int lane = t & 31, w = t >> 5;
    int inc = v;
#pragma unroll
    for (int o = 1; o < 32; o <<= 1) {
        int u = __shfl_up_sync(0xFFFFFFFFu, inc, o);
        if (lane >= o) inc += u;
    }
    if (lane == 31) wsum[w] = inc;
    __syncthreads();
    if (w == 0) {
        int s = (lane < 16) ? wsum[lane] : 0;
#pragma unroll
        for (int o = 1; o < 16; o <<= 1) {
            int u = __shfl_up_sync(0xFFFFFFFFu, s, o);
            if (lane >= o) s += u;
        }
        if (lane < 16) wsum[lane] = s;
    }
    __syncthreads();
    int wbase = (w > 0) ? wsum[w - 1] : 0;
    if (i < NN) g_rowptr[i] = wbase + inc - v;
    if (t == 0) g_bsum[blockIdx.x] = wsum[15];
}

// Stage B: exclusive scan of 98 block sums.
__global__ void k_scanB() {
    __shared__ int ws[4];
    int t = threadIdx.x, lane = t & 31, w = t >> 5;
    int v = (t < NBLK) ? g_bsum[t] : 0;
    int inc = v;
#pragma unroll
    for (int o = 1; o < 32; o <<= 1) {
        int u = __shfl_up_sync(0xFFFFFFFFu, inc, o);
        if (lane >= o) inc += u;
    }
    if (lane == 31) ws[w] = inc;
    __syncthreads();
    if (t == 0) {
        int s = 0;
#pragma unroll
        for (int k = 0; k < 4; k++) { int x = ws[k]; ws[k] = s; s += x; }
    }
    __syncthreads();
    if (t < NBLK) g_boff[t] = ws[w] + inc - v;
    if (t == 0) g_rowptr[NN] = NE;
}

// Stage C: add block offsets.
__global__ void k_scanC() {
    int i = blockIdx.x * blockDim.x + threadIdx.x;
    if (i < NN) g_rowptr[i] += g_boff[i / SCB];
}

__global__ void k_fill(const int* __restrict__ ei, const float* __restrict__ ew) {
    int e = blockIdx.x * blockDim.x + threadIdx.x;
    if (e < NE) {
        int r = ei[e];
        int c = ei[NE + e];
        float w = ew[e] * g_dinv[r] * g_dinv[c];
        int p = g_rowptr[r] + atomicAdd(&g_fill[r], 1);
        g_edge[p] = make_float2(__int_as_float(c), w);
    }
}

// ---------------- GEMM1: x1 = x @ W1; writes fp32 g_x1 and fp16 g_sA ----------------
__global__ void __launch_bounds__(256) k_gemm1(const float* __restrict__ x,
                                               const float* __restrict__ W1) {
    __shared__ float W1s[64 * 64];
    __shared__ float xs[64 * 68];
    int t  = threadIdx.x;
    int tx = t & 15;
    int ty = t >> 4;
    int nb = blockIdx.x * 64;

    float acc[4][4];
#pragma unroll
    for (int i = 0; i < 4; i++)
#pragma unroll
        for (int j = 0; j < 4; j++) acc[i][j] = 0.0f;

    for (int kh = 0; kh < 2; kh++) {
        __syncthreads();
        for (int i = t; i < 1024; i += 256)
            ((float4*)W1s)[i] = ((const float4*)(W1 + kh * 64 * 64))[i];
        for (int i = t; i < 1024; i += 256) {
            int r  = i >> 4;
            int kk = (i & 15) << 2;
            int n  = nb + r;
            float4 v = make_float4(0.f, 0.f, 0.f, 0.f);
            if (n < NN) v = *(const float4*)(x + n * FI + kh * 64 + kk);
            *(float4*)(xs + r * 68 + kk) = v;
        }
        __syncthreads();
#pragma unroll 8
        for (int k = 0; k < 64; k++) {
            float4 b4 = *(const float4*)(W1s + k * 64 + tx * 4);
#pragma unroll
            for (int i = 0; i < 4; i++) {
                float a = xs[(ty * 4 + i) * 68 + k];
                acc[i][0] += a * b4.x;
                acc[i][1] += a * b4.y;
                acc[i][2] += a * b4.z;
                acc[i][3] += a * b4.w;
            }
        }
    }
#pragma unroll
    for (int i = 0; i < 4; i++) {
        int n = nb + ty * 4 + i;
        if (n < NN) {
            *(float4*)(g_x1 + n * HD + tx * 4) =
                make_float4(acc[i][0], acc[i][1], acc[i][2], acc[i][3]);
            g_sA[n * 32 + tx * 2]     = __floats2half2_rn(acc[i][0], acc[i][1]);
            g_sA[n * 32 + tx * 2 + 1] = __floats2half2_rn(acc[i][2], acc[i][3]);
        }
    }
}

// ---------------- SpMM hop: warp per row, lane = one half2; fp32 acc RMW fused -------
__global__ void __launch_bounds__(256) k_hop(int srcA, int first) {
    int gw   = (blockIdx.x * blockDim.x + threadIdx.x) >> 5;
    int lane = threadIdx.x & 31;
    if (gw >= NN) return;

    const __half2* __restrict__ s = srcA ? g_sA : g_sB;
    __half2* __restrict__ d = srcA ? g_sB : g_sA;

    int beg = g_rowptr[gw];
    int end = g_rowptr[gw + 1];

    float di = g_dinv[gw];
    float sw = di * di;                   // self-loop weight
    float2 self = __half22float2(s[gw * 32 + lane]);
    float ax = sw * self.x;
    float ay = sw * self.y;

    int e = beg;
    for (; e + 3 < end; e += 4) {
        float2 cw0 = g_edge[e];
        float2 cw1 = g_edge[e + 1];
        float2 cw2 = g_edge[e + 2];
        float2 cw3 = g_edge[e + 3];
        float2 h0 = __half22float2(s[__float_as_int(cw0.x) * 32 + lane]);
        float2 h1 = __half22float2(s[__float_as_int(cw1.x) * 32 + lane]);
        float2 h2 = __half22float2(s[__float_as_int(cw2.x) * 32 + lane]);
        float2 h3 = __half22float2(s[__float_as_int(cw3.x) * 32 + lane]);
        ax += cw0.y * h0.x + cw1.y * h1.x;
        ay += cw0.y * h0.y + cw1.y * h1.y;
        ax += cw2.y * h2.x + cw3.y * h3.x;
        ay += cw2.y * h2.y + cw3.y * h3.y;
    }
    for (; e < end; e++) {
        float2 cw = g_edge[e];
        float2 h0 = __half22float2(s[__float_as_int(cw.x) * 32 + lane]);
        ax += cw.y * h0.x;
        ay += cw.y * h0.y;
    }

    d[gw * 32 + lane] = __floats2half2_rn(ax, ay);
    float2* ac = (float2*)g_acc;
    if (first) {
        ac[gw * 32 + lane] = make_float2(ax, ay);
    } else {
        float2 p = ac[gw * 32 + lane];
        ac[gw * 32 + lane] = make_float2(p.x + ax, p.y + ay);
    }
}

// ---------------- final: z = relu(0.09*acc + 0.1*x1 + b1); out = z @ W2 + b2 ----------
__global__ void __launch_bounds__(320) k_final(const float* __restrict__ b1,
                                               const float* __restrict__ W2,
                                               const float* __restrict__ b2,
                                               float* __restrict__ out) {
    __shared__ float W2t[NC * 68];
    __shared__ float zs[8 * 64];
    __shared__ float b1s[HD];

    int t = threadIdx.x;
    for (int i = t; i < HD * NC; i += 320) {
        int k = i / NC, c = i % NC;
        W2t[c * 68 + k] = W2[i];
    }
    if (t < HD) b1s[t] = b1[t];

    int node = t / NC;
    int cls  = t % NC;
    float b2v = b2[cls];
    __syncthreads();

    const float C1 = (1.0f - 0.1f) / 10.0f;  // 0.09
    const float C2 = 0.1f;
    int nb0 = blockIdx.x * 400;

    for (int it = 0; it < 50; it++) {
        int nb = nb0 + it * 8;
        {
            int i = t;
            int n = nb + (i >> 6), f = i & 63;
            zs[i] = fmaxf(C1 * g_acc[n * HD + f] + C2 * g_x1[n * HD + f] + b1s[f], 0.0f);
            i = t + 320;
            if (i < 512) {
                n = nb + (i >> 6); f = i & 63;
                zs[i] = fmaxf(C1 * g_acc[n * HD + f] + C2 * g_x1[n * HD + f] + b1s[f], 0.0f);
            }
        }
        __syncthreads();
        float s = b2v;
        const float* zr = zs + node * 64;
        const float* wr = W2t + cls * 68;
#pragma unroll
        for (int k = 0; k < 64; k += 4) {
            float4 zv = *(const float4*)(zr + k);
            float4 wv = *(const float4*)(wr + k);
            s += zv.x * wv.x + zv.y * wv.y + zv.z * wv.z + zv.w * wv.w;
        }
        out[(nb + node) * NC + cls] = s;
        __syncthreads();
    }
}

// ---------------- launch ----------------
extern "C" void kernel_launch(void* const* d_in, const int* in_sizes, int n_in,
                              void* d_out, int out_size) {
    const float* x  = (const float*)d_in[0];
    const int*   ei = (const int*)d_in[1];    // [2, NE]
    const float* ew = (const float*)d_in[2];
    const float* W1 = (const float*)d_in[3];  // [128, 64]
    const float* b1 = (const float*)d_in[4];
    const float* W2 = (const float*)d_in[5];  // [64, 40]
    const float* b2 = (const float*)d_in[6];
    float* out = (float*)d_out;

    k_init  <<<(NN + 255) / 256, 256>>>();
    k_degree<<<(NE + 255) / 256, 256>>>(ei, ew);
    k_scanA <<<NBLK, SCB>>>();
    k_scanB <<<1, 128>>>();
    k_scanC <<<(NN + 255) / 256, 256>>>();
    k_fill  <<<(NE + 255) / 256, 256>>>(ei, ew);
    k_gemm1 <<<(NN + 63) / 64, 256>>>(x, W1);

    int hop_blocks = (NN * 32 + 255) / 256;  // 6250
    for (int i = 0; i < KH; i++)
        k_hop<<<hop_blocks, 256>>>((i & 1) == 0, i == 0);

    k_final<<<125, 320>>>(b1, W2, b2, out);
}